// round 9
// baseline (speedup 1.0000x reference)
#include <cuda_runtime.h>
#include <cstdint>

// Problem constants
#define BB    8
#define C     128
#define W     256
#define H     256
#define NPIX  (W*H)          // 65536 pixels per image
#define NBLK  512
#define NB7   64             // b7 tile blocks (0..63)
#define NCHUNK 16            // chunks per b7 tile
#define CF4   16             // float4-pixels per chunk
#define CPAD  17             // padded f4 stride per channel row (bank-magic)

// Output buffer layout (concatenated f32, raw reshapes):
#define OFF_CENTERS 0
#define OFF_LABELS  256
#define OFF_ONEHOT  (OFF_LABELS + BB*NPIX)
#define OFF_DIST    (OFF_ONEHOT + BB*2*NPIX)
#define OFF_LABELT  (OFF_DIST   + BB*2*NPIX)

// Scratch (__device__ globals; overwrite slots, counter self-resets).
__device__ float g_part[NB7 * 256];  // [slot*256 + k*128 + ch]
__device__ int   g_cntp[NB7];        // per-slot label==1 count
__device__ int   g_arrive = 0;       // terminal arrival counter

// ---------------------------------------------------------------------------
// Streaming main tile for batches 0..6 (the proven roofline path).
// ---------------------------------------------------------------------------
__device__ __forceinline__ void main_tile_stream(const float* __restrict__ F,
                                                 const float* __restrict__ sc,
                                                 float* __restrict__ out,
                                                 int b, int p4) {
    int n0 = p4 << 2;
    const float4* Fb = reinterpret_cast<const float4*>(F + (size_t)b * C * NPIX);

    float4 a0 = make_float4(0.f,0.f,0.f,0.f);
    float4 a1 = make_float4(0.f,0.f,0.f,0.f);
    #pragma unroll 8
    for (int ch = 0; ch < C; ch++) {
        float4 f = __ldcs(&Fb[ch * (NPIX/4) + p4]);
        float c0 = sc[ch], c1 = sc[C + ch];
        a0.x += f.x*c0; a0.y += f.y*c0; a0.z += f.z*c0; a0.w += f.w*c0;
        a1.x += f.x*c1; a1.y += f.y*c1; a1.z += f.z*c1; a1.w += f.w*c1;
    }

    float d0x = 0.5f - 0.5f*a0.x, d1x = 0.5f - 0.5f*a1.x;
    float d0y = 0.5f - 0.5f*a0.y, d1y = 0.5f - 0.5f*a1.y;
    float d0z = 0.5f - 0.5f*a0.z, d1z = 0.5f - 0.5f*a1.z;
    float d0w = 0.5f - 0.5f*a0.w, d1w = 0.5f - 0.5f*a1.w;

    int lx = d1x < d0x, ly = d1y < d0y, lz = d1z < d0z, lw = d1w < d0w;
    float4 lab = make_float4((float)lx, (float)ly, (float)lz, (float)lw);

    __stcs(reinterpret_cast<float4*>(out + OFF_LABELS + (size_t)b*NPIX + n0), lab);
    __stcs(reinterpret_cast<float4*>(out + OFF_LABELT + (size_t)b*NPIX + n0), lab);

    float4* outO = reinterpret_cast<float4*>(out + OFF_ONEHOT + (size_t)b*2*NPIX + 2*n0);
    __stcs(outO + 0, make_float4(1.f - lab.x, lab.x, 1.f - lab.y, lab.y));
    __stcs(outO + 1, make_float4(1.f - lab.z, lab.z, 1.f - lab.w, lab.w));

    float4* outD = reinterpret_cast<float4*>(out + OFF_DIST + (size_t)b*2*NPIX + 2*n0);
    __stcs(outD + 0, make_float4(d0x, d1x, d0y, d1y));
    __stcs(outD + 1, make_float4(d0z, d1z, d0w, d1w));
}

// ---------------------------------------------------------------------------
// Single kernel, 512 blocks x 256 threads, one wave.
// Blocks 0..63  : b7 tile via smem chunks — F7 read ONCE; dot + labels +
//                 outputs + masked channel sums all from the cached chunk.
// Blocks 64..511: streaming b0..6 tiles.
// Only inter-block sync: terminal arrival for the centers epilogue.
// ---------------------------------------------------------------------------
__global__ void __launch_bounds__(256, 4)
k_all(const float* __restrict__ F,
      const float* __restrict__ Cinit,
      float* __restrict__ out) {
    __shared__ float  sc[2*C];
    __shared__ float4 schunk[C * CPAD];   // 128ch x (16+1 pad) f4 = 34816 B
    __shared__ float4 slab[CF4];          // labels per f4-pixel of the chunk
    __shared__ int    s_done;

    int t    = threadIdx.x;
    int blk  = blockIdx.x;

    sc[t] = Cinit[t];
    __syncthreads();

    if (blk < NB7) {
        // ================= b7 tile: single-read smem pipeline ==============
        int slot  = blk;
        int base4 = slot * 256;            // tile start (f4-pixel index)
        const float4* F7 = reinterpret_cast<const float4*>(
            F + (size_t)(BB-1) * C * NPIX);

        float4* L4 = reinterpret_cast<float4*>(out + OFF_LABELS + (size_t)(BB-1)*NPIX);
        float4* T4 = reinterpret_cast<float4*>(out + OFF_LABELT + (size_t)(BB-1)*NPIX);
        float4* O4 = reinterpret_cast<float4*>(out + OFF_ONEHOT + (size_t)(BB-1)*2*NPIX);
        float4* D4 = reinterpret_cast<float4*>(out + OFF_DIST   + (size_t)(BB-1)*2*NPIX);

        // per-thread accumulators across chunks
        float sa_acc = 0.f, s1_acc = 0.f;      // channel ch = t&127, half h = t>>7
        float cnt_acc = 0.f;                   // threads 0..15 only
        int chS = t & 127, h = t >> 7;         // step-4 mapping
        int p   = t >> 4,  s = t & 15;         // dot mapping: pixel p, sub s

        for (int c = 0; c < NCHUNK; c++) {
            int cbase = base4 + c * CF4;
            __syncthreads();                   // smem free from prev chunk

            // --- load chunk: 2048 f4, 8 per thread, coalesced 256B runs ---
            #pragma unroll
            for (int j = 0; j < 8; j++) {
                int id = t + 256*j;            // ch = id>>4, i = id&15
                int ch = id >> 4, i = id & 15;
                schunk[ch*CPAD + i] = __ldcs(&F7[(size_t)ch * (NPIX/4) + cbase + i]);
            }
            __syncthreads();

            // --- dot: 16 subs per pixel, 8 channels each ---
            float a0x=0.f,a0y=0.f,a0z=0.f,a0w=0.f;
            float a1x=0.f,a1y=0.f,a1z=0.f,a1w=0.f;
            #pragma unroll
            for (int k = 0; k < 8; k++) {
                int ch = s + 16*k;
                float4 f = schunk[ch*CPAD + p];
                float c0 = sc[ch], c1 = sc[C + ch];
                a0x += f.x*c0; a0y += f.y*c0; a0z += f.z*c0; a0w += f.w*c0;
                a1x += f.x*c1; a1y += f.y*c1; a1z += f.z*c1; a1w += f.w*c1;
            }
            #pragma unroll
            for (int o = 1; o <= 8; o <<= 1) {     // reduce over 16 subs
                a0x += __shfl_xor_sync(0xffffffffu, a0x, o);
                a0y += __shfl_xor_sync(0xffffffffu, a0y, o);
                a0z += __shfl_xor_sync(0xffffffffu, a0z, o);
                a0w += __shfl_xor_sync(0xffffffffu, a0w, o);
                a1x += __shfl_xor_sync(0xffffffffu, a1x, o);
                a1y += __shfl_xor_sync(0xffffffffu, a1y, o);
                a1z += __shfl_xor_sync(0xffffffffu, a1z, o);
                a1w += __shfl_xor_sync(0xffffffffu, a1w, o);
            }
            if (s == 0) {
                float d0x = 0.5f - 0.5f*a0x, d1x = 0.5f - 0.5f*a1x;
                float d0y = 0.5f - 0.5f*a0y, d1y = 0.5f - 0.5f*a1y;
                float d0z = 0.5f - 0.5f*a0z, d1z = 0.5f - 0.5f*a1z;
                float d0w = 0.5f - 0.5f*a0w, d1w = 0.5f - 0.5f*a1w;
                float4 lab = make_float4((float)(d1x<d0x), (float)(d1y<d0y),
                                         (float)(d1z<d0z), (float)(d1w<d0w));
                slab[p] = lab;
                int g = cbase + p;                       // global f4-pixel index
                __stcs(&L4[g], lab);
                __stcs(&T4[g], lab);
                __stcs(&O4[2*g],   make_float4(1.f-lab.x, lab.x, 1.f-lab.y, lab.y));
                __stcs(&O4[2*g+1], make_float4(1.f-lab.z, lab.z, 1.f-lab.w, lab.w));
                __stcs(&D4[2*g],   make_float4(d0x, d1x, d0y, d1y));
                __stcs(&D4[2*g+1], make_float4(d0z, d1z, d0w, d1w));
            }
            __syncthreads();                   // slab visible; schunk intact

            // --- masked channel sums from the cached chunk ---
            #pragma unroll
            for (int m = 0; m < 8; m++) {
                int i = h*8 + m;
                float4 f = schunk[chS*CPAD + i];
                float4 l = slab[i];
                sa_acc += f.x + f.y + f.z + f.w;
                s1_acc += f.x*l.x + f.y*l.y + f.z*l.z + f.w*l.w;
            }
            if (t < CF4) {                     // count from this chunk's labels
                float4 l = slab[t];
                cnt_acc += l.x + l.y + l.z + l.w;
            }
        }

        // --- per-slot writes: combine halves, write unique slots ---
        __syncthreads();
        float* red = reinterpret_cast<float*>(schunk);
        red[t]       = sa_acc;
        red[256 + t] = s1_acc;
        __syncthreads();
        if (t < C) {
            float sa = red[t] + red[t + 128];
            float s1 = red[256 + t] + red[256 + t + 128];
            g_part[slot*256 + t]       = sa - s1;   // label 0
            g_part[slot*256 + 128 + t] = s1;        // label 1
        }
        if (t < CF4) {
            #pragma unroll
            for (int o = 1; o <= 8; o <<= 1)
                cnt_acc += __shfl_xor_sync(0x0000ffffu, cnt_acc, o);
            if (t == 0) g_cntp[slot] = (int)cnt_acc;
        }
    } else {
        // ================= streaming tiles, batches 0..6 ===================
        int tile = blk - NB7;                 // 0..447
        int b    = tile >> 6;
        int slot = tile & 63;
        main_tile_stream(F, sc, out, b, slot * 256 + t);
    }

    // ---------------- terminal arrival; last block: epilogue ---------------
    __syncthreads();
    if (t == 0) {
        __threadfence();
        int old = atomicAdd(&g_arrive, 1);
        s_done = (old == NBLK - 1);
    }
    __syncthreads();
    if (!s_done) return;
    __threadfence();

    int cnt = 0;
    #pragma unroll 8
    for (int s2 = 0; s2 < NB7; s2++) cnt += g_cntp[s2];
    float sum = 0.f;
    #pragma unroll 8
    for (int s2 = 0; s2 < NB7; s2++) sum += g_part[s2*256 + t];

    int k = t >> 7;
    float num = (k ? (float)cnt : (float)(NPIX - cnt)) + 1.0f;
    float mean = sum / num;
    float ci = sc[t];
    out[OFF_CENTERS + t] = ci + 0.001f * (mean - ci);

    if (t == 0) g_arrive = 0;                 // reset for next graph replay
}

// ---------------------------------------------------------------------------
extern "C" void kernel_launch(void* const* d_in, const int* in_sizes, int n_in,
                              void* d_out, int out_size) {
    const float* F     = (const float*)d_in[0];   // FeatureT [8,128,256,256]
    const float* Cinit = (const float*)d_in[1];   // centerInit [2,128]
    float* out = (float*)d_out;
    (void)in_sizes; (void)n_in; (void)out_size;

    k_all<<<NBLK, 256>>>(F, Cinit, out);
}

// round 11
// speedup vs baseline: 1.2944x; 1.2944x over previous
#include <cuda_runtime.h>
#include <cstdint>

// Problem constants
#define BB    8
#define C     128
#define W     256
#define H     256
#define NPIX  (W*H)          // 65536 pixels per image
#define NB7   128            // b7 half-tile blocks (512 px each)
#define NMAIN 448            // b0..6 tiles (1024 px each)
#define NBLK  (NB7 + NMAIN)  // 576 total; one wave (<=592 at 4/SM)

// Output buffer layout (concatenated f32, raw reshapes):
#define OFF_CENTERS 0
#define OFF_LABELS  256
#define OFF_ONEHOT  (OFF_LABELS + BB*NPIX)
#define OFF_DIST    (OFF_ONEHOT + BB*2*NPIX)
#define OFF_LABELT  (OFF_DIST   + BB*2*NPIX)

// Scratch (__device__ globals; overwrite slots, counter self-resets).
__device__ float g_part[NB7 * 256];  // [slot*256 + k*128 + ch]
__device__ int   g_cntp[NB7];        // per-slot label==1 count
__device__ int   g_arrive = 0;       // terminal arrival counter

// ---------------------------------------------------------------------------
// Streaming main tile for batches 0..6 (the proven roofline path, unchanged).
// ---------------------------------------------------------------------------
__device__ __forceinline__ void main_tile_stream(const float* __restrict__ F,
                                                 const float* __restrict__ sc,
                                                 float* __restrict__ out,
                                                 int b, int p4) {
    int n0 = p4 << 2;
    const float4* Fb = reinterpret_cast<const float4*>(F + (size_t)b * C * NPIX);

    float4 a0 = make_float4(0.f,0.f,0.f,0.f);
    float4 a1 = make_float4(0.f,0.f,0.f,0.f);
    #pragma unroll 8
    for (int ch = 0; ch < C; ch++) {
        float4 f = __ldcs(&Fb[ch * (NPIX/4) + p4]);
        float c0 = sc[ch], c1 = sc[C + ch];
        a0.x += f.x*c0; a0.y += f.y*c0; a0.z += f.z*c0; a0.w += f.w*c0;
        a1.x += f.x*c1; a1.y += f.y*c1; a1.z += f.z*c1; a1.w += f.w*c1;
    }

    float d0x = 0.5f - 0.5f*a0.x, d1x = 0.5f - 0.5f*a1.x;
    float d0y = 0.5f - 0.5f*a0.y, d1y = 0.5f - 0.5f*a1.y;
    float d0z = 0.5f - 0.5f*a0.z, d1z = 0.5f - 0.5f*a1.z;
    float d0w = 0.5f - 0.5f*a0.w, d1w = 0.5f - 0.5f*a1.w;

    int lx = d1x < d0x, ly = d1y < d0y, lz = d1z < d0z, lw = d1w < d0w;
    float4 lab = make_float4((float)lx, (float)ly, (float)lz, (float)lw);

    __stcs(reinterpret_cast<float4*>(out + OFF_LABELS + (size_t)b*NPIX + n0), lab);
    __stcs(reinterpret_cast<float4*>(out + OFF_LABELT + (size_t)b*NPIX + n0), lab);

    float4* outO = reinterpret_cast<float4*>(out + OFF_ONEHOT + (size_t)b*2*NPIX + 2*n0);
    __stcs(outO + 0, make_float4(1.f - lab.x, lab.x, 1.f - lab.y, lab.y));
    __stcs(outO + 1, make_float4(1.f - lab.z, lab.z, 1.f - lab.w, lab.w));

    float4* outD = reinterpret_cast<float4*>(out + OFF_DIST + (size_t)b*2*NPIX + 2*n0);
    __stcs(outD + 0, make_float4(d0x, d1x, d0y, d1y));
    __stcs(outD + 1, make_float4(d0z, d1z, d0w, d1w));
}

// ---------------------------------------------------------------------------
// Single kernel, 576 blocks x 256 threads. ZERO inter-block waits.
// Blocks 0..127  : b7 half-tile (512 px). Phase 1 dot with 2-sub channel
//                  split (all warps active), labels in smem; then a local
//                  masked channel-sum pass over OWN 256KB (L2-hot, long
//                  per-channel runs). Finishes early; rides under the stream.
// Blocks 128..575: streaming b0..6 tiles (the roofline path).
// Terminal arrival only (non-blocking); last block writes centers + resets.
// ---------------------------------------------------------------------------
__global__ void __launch_bounds__(256, 4)
k_all(const float* __restrict__ F,
      const float* __restrict__ Cinit,
      float* __restrict__ out) {
    __shared__ float  sc[2*C];
    __shared__ float4 slab[NB7 > 0 ? 128 : 1];   // labels per f4-pixel of tile
    __shared__ int    s_done;

    int t    = threadIdx.x;
    int lane = t & 31;
    int warp = t >> 5;
    int blk  = blockIdx.x;

    sc[t] = Cinit[t];
    __syncthreads();

    if (blk < NB7) {
        // ================= b7 half-tile, fully self-contained ==============
        int slot  = blk;
        int base4 = slot * 128;              // 128 f4-pixels (512 px)
        const float4* F7 = reinterpret_cast<const float4*>(
            F + (size_t)(BB-1) * C * NPIX);

        // --- Phase 1: p = t>>1 (f4 pixel), s = t&1 (channel half) ---
        int p  = t >> 1;
        int s  = t & 1;
        int p4 = base4 + p;

        float a0x=0.f,a0y=0.f,a0z=0.f,a0w=0.f;
        float a1x=0.f,a1y=0.f,a1z=0.f,a1w=0.f;
        #pragma unroll 8
        for (int k = 0; k < 64; k++) {
            int ch = s*64 + k;
            float4 f = F7[(size_t)ch * (NPIX/4) + p4];   // default: L2-retain
            float c0 = sc[ch], c1 = sc[C + ch];
            a0x += f.x*c0; a0y += f.y*c0; a0z += f.z*c0; a0w += f.w*c0;
            a1x += f.x*c1; a1y += f.y*c1; a1z += f.z*c1; a1w += f.w*c1;
        }
        // combine the two channel halves (xor partner lane)
        a0x += __shfl_xor_sync(0xffffffffu, a0x, 1);
        a0y += __shfl_xor_sync(0xffffffffu, a0y, 1);
        a0z += __shfl_xor_sync(0xffffffffu, a0z, 1);
        a0w += __shfl_xor_sync(0xffffffffu, a0w, 1);
        a1x += __shfl_xor_sync(0xffffffffu, a1x, 1);
        a1y += __shfl_xor_sync(0xffffffffu, a1y, 1);
        a1z += __shfl_xor_sync(0xffffffffu, a1z, 1);
        a1w += __shfl_xor_sync(0xffffffffu, a1w, 1);

        float d0x = 0.5f - 0.5f*a0x, d1x = 0.5f - 0.5f*a1x;
        float d0y = 0.5f - 0.5f*a0y, d1y = 0.5f - 0.5f*a1y;
        float d0z = 0.5f - 0.5f*a0z, d1z = 0.5f - 0.5f*a1z;
        float d0w = 0.5f - 0.5f*a0w, d1w = 0.5f - 0.5f*a1w;
        float4 lab = make_float4((float)(d1x<d0x), (float)(d1y<d0y),
                                 (float)(d1z<d0z), (float)(d1w<d0w));

        float4* L4 = reinterpret_cast<float4*>(out + OFF_LABELS + (size_t)(BB-1)*NPIX);
        float4* T4 = reinterpret_cast<float4*>(out + OFF_LABELT + (size_t)(BB-1)*NPIX);
        float4* O4 = reinterpret_cast<float4*>(out + OFF_ONEHOT + (size_t)(BB-1)*2*NPIX);
        float4* D4 = reinterpret_cast<float4*>(out + OFF_DIST   + (size_t)(BB-1)*2*NPIX);
        int g = p4;
        if (s == 0) {
            slab[p] = lab;
            __stcs(&L4[g], lab);
            __stcs(&O4[2*g],   make_float4(1.f-lab.x, lab.x, 1.f-lab.y, lab.y));
            __stcs(&D4[2*g],   make_float4(d0x, d1x, d0y, d1y));
        } else {
            __stcs(&T4[g], lab);
            __stcs(&O4[2*g+1], make_float4(1.f-lab.z, lab.z, 1.f-lab.w, lab.w));
            __stcs(&D4[2*g+1], make_float4(d0z, d1z, d0w, d1w));
        }
        __syncthreads();                      // slab complete

        // --- label-1 count for this half-tile (warp 0) ---
        if (warp == 0) {
            float c = 0.f;
            #pragma unroll
            for (int i = 0; i < 4; i++) {
                float4 l = slab[lane + 32*i];
                c += l.x + l.y + l.z + l.w;
            }
            #pragma unroll
            for (int o = 16; o > 0; o >>= 1)
                c += __shfl_down_sync(0xffffffffu, c, o);
            if (lane == 0) g_cntp[slot] = (int)c;
        }

        // --- local masked channel sums (own 256KB, L2-hot, long runs) ---
        #pragma unroll 2
        for (int j = 0; j < 16; j++) {
            int ch = warp + 8*j;
            const float4* row = F7 + (size_t)ch * (NPIX/4) + base4;
            float sa = 0.f, s1 = 0.f;
            #pragma unroll
            for (int i = 0; i < 4; i++) {
                float4 f = row[lane + 32*i];
                float4 l = slab[lane + 32*i];
                sa += f.x + f.y + f.z + f.w;
                s1 += f.x*l.x + f.y*l.y + f.z*l.z + f.w*l.w;
            }
            #pragma unroll
            for (int o = 16; o > 0; o >>= 1) {
                sa += __shfl_down_sync(0xffffffffu, sa, o);
                s1 += __shfl_down_sync(0xffffffffu, s1, o);
            }
            if (lane == 0) {
                g_part[slot*256 + ch]       = sa - s1;   // label 0
                g_part[slot*256 + 128 + ch] = s1;        // label 1
            }
        }
    } else {
        // ================= streaming tiles, batches 0..6 ===================
        int tile = blk - NB7;                 // 0..447
        int b    = tile >> 6;
        int slot = tile & 63;
        main_tile_stream(F, sc, out, b, slot * 256 + t);
    }

    // ---------------- terminal arrival; last block: epilogue ---------------
    __syncthreads();
    if (t == 0) {
        __threadfence();
        int old = atomicAdd(&g_arrive, 1);
        s_done = (old == NBLK - 1);
    }
    __syncthreads();
    if (!s_done) return;
    __threadfence();

    int cnt = 0;
    #pragma unroll 8
    for (int s2 = 0; s2 < NB7; s2++) cnt += g_cntp[s2];
    float sum = 0.f;
    #pragma unroll 8
    for (int s2 = 0; s2 < NB7; s2++) sum += g_part[s2*256 + t];

    int k = t >> 7;
    float num = (k ? (float)cnt : (float)(NPIX - cnt)) + 1.0f;
    float mean = sum / num;
    float ci = sc[t];
    out[OFF_CENTERS + t] = ci + 0.001f * (mean - ci);

    if (t == 0) g_arrive = 0;                 // reset for next graph replay
}

// ---------------------------------------------------------------------------
extern "C" void kernel_launch(void* const* d_in, const int* in_sizes, int n_in,
                              void* d_out, int out_size) {
    const float* F     = (const float*)d_in[0];   // FeatureT [8,128,256,256]
    const float* Cinit = (const float*)d_in[1];   // centerInit [2,128]
    float* out = (float*)d_out;
    (void)in_sizes; (void)n_in; (void)out_size;

    k_all<<<NBLK, 256>>>(F, Cinit, out);
}